// round 2
// baseline (speedup 1.0000x reference)
#include <cuda_runtime.h>

// Problem constants (fixed shapes for this dataset entry)
#define MAXN 100000
#define MAXE 1600000
#define MAXTOT (MAXN + MAXE)
#define IN_C 128
#define HID 32
#define HEADS 4
#define OUT_C 16
#define NEG_SLOPE 0.2f

// ---------------- scratch (device globals; no runtime allocation) ----------
__device__ __align__(16) float g_h1[MAXN * 128];    // layer-1 transformed features
__device__ __align__(16) float g_als1[MAXN * 4];
__device__ __align__(16) float g_ald1[MAXN * 4];
__device__ __align__(16) float g_x2[MAXN * 128];    // relu(layer-1 out) = layer-2 input
__device__ __align__(16) float g_h2[MAXN * 16];
__device__ float g_als2[MAXN];
__device__ float g_ald2[MAXN];
__device__ int g_deg[MAXN];
__device__ int g_rowptr[MAXN + 1];
__device__ int g_cursor[MAXN];
__device__ int g_col[MAXTOT];
__device__ int g_src[MAXE];
__device__ int g_dst[MAXE];
__device__ int g_is64;

// ---------------- f32x2 packed helpers (Blackwell) --------------------------
__device__ __forceinline__ unsigned long long pack2(float a, float b) {
    unsigned long long r;
    asm("mov.b64 %0, {%1, %2};" : "=l"(r) : "f"(a), "f"(b));
    return r;
}
__device__ __forceinline__ void fma2(unsigned long long& d, unsigned long long a,
                                     unsigned long long b) {
    asm("fma.rn.f32x2 %0, %1, %2, %0;" : "+l"(d) : "l"(a), "l"(b));
}
__device__ __forceinline__ float2 unpack2(unsigned long long v) {
    float2 f;
    asm("mov.b64 {%0, %1}, %2;" : "=f"(f.x), "=f"(f.y) : "l"(v));
    return f;
}

// ---------------- edge-index dtype probe + normalize ------------------------
// If the buffer is int64 (little-endian, values < 2^17), the odd int32 words of
// the first entries are all zero. If it is int32, they are random node ids.
__global__ void k_probe(const int* __restrict__ ei32, int E) {
    if (threadIdx.x == 0 && blockIdx.x == 0) {
        int cnt = E < 64 ? E : 64;
        int zeros = 0;
        for (int i = 0; i < cnt; i++) zeros += (ei32[2 * i + 1] == 0) ? 1 : 0;
        g_is64 = (zeros == cnt) ? 1 : 0;
    }
}

__global__ void k_convert(const void* __restrict__ ei, int E, int N) {
    int e = blockIdx.x * blockDim.x + threadIdx.x;
    if (e >= E) return;
    int s, d;
    if (g_is64) {
        const long long* p = (const long long*)ei;
        s = (int)p[e];
        d = (int)p[E + e];
    } else {
        const int* p = (const int*)ei;
        s = p[e];
        d = p[E + e];
    }
    // defensive clamp: never let bad data produce a wild address
    s = min(max(s, 0), N - 1);
    d = min(max(d, 0), N - 1);
    g_src[e] = s;
    g_dst[e] = d;
}

// ---------------- CSR build --------------------------------------------------
__global__ void k_deg_init(int n) {
    int i = blockIdx.x * blockDim.x + threadIdx.x;
    if (i < n) g_deg[i] = 1;  // self loop
}

__global__ void k_deg_count(int E) {
    int e = blockIdx.x * blockDim.x + threadIdx.x;
    if (e < E) atomicAdd(&g_deg[g_dst[e]], 1);
}

__global__ void k_scan(int n) {
    __shared__ int ssum[1024];
    int t = threadIdx.x;
    int chunk = (n + 1023) / 1024;
    int b = t * chunk; if (b > n) b = n;
    int e = b + chunk; if (e > n) e = n;
    int s = 0;
    for (int i = b; i < e; i++) s += g_deg[i];
    ssum[t] = s;
    __syncthreads();
    for (int off = 1; off < 1024; off <<= 1) {
        int v = (t >= off) ? ssum[t - off] : 0;
        __syncthreads();
        ssum[t] += v;
        __syncthreads();
    }
    int run = ssum[t] - s;  // exclusive prefix for this chunk
    for (int i = b; i < e; i++) {
        g_rowptr[i] = run;
        g_cursor[i] = run;
        run += g_deg[i];
    }
    if (t == 1023) g_rowptr[n] = ssum[1023];
}

__global__ void k_self(int n) {
    int i = blockIdx.x * blockDim.x + threadIdx.x;
    if (i < n) {
        int pos = atomicAdd(&g_cursor[i], 1);
        g_col[pos] = i;
    }
}

__global__ void k_fill(int E) {
    int e = blockIdx.x * blockDim.x + threadIdx.x;
    if (e < E) {
        int pos = atomicAdd(&g_cursor[g_dst[e]], 1);
        g_col[pos] = g_src[e];
    }
}

// ---------------- GEMM1: h1 = x @ W1, fused a_src/a_dst dots ----------------
__global__ void k_gemm1(const float* __restrict__ x, const float* __restrict__ W,
                        const float* __restrict__ asrc, const float* __restrict__ adst,
                        int n) {
    __shared__ float xs[64 * 132];  // padded stride to kill bank conflicts
    __shared__ float ws[32 * 128];
    int t = threadIdx.x;
    int row0 = blockIdx.x * 64;

    for (int i = t; i < 64 * 32; i += 256) {
        int r = i >> 5, cq = i & 31;
        float4 v = make_float4(0.f, 0.f, 0.f, 0.f);
        if (row0 + r < n) v = *(const float4*)&x[(size_t)(row0 + r) * 128 + cq * 4];
        *(float4*)&xs[r * 132 + cq * 4] = v;
    }

    unsigned long long acc[16];
#pragma unroll
    for (int i = 0; i < 16; i++) acc[i] = pack2(0.f, 0.f);

    int rl = t >> 2, colq = t & 3;
    for (int kc = 0; kc < 128; kc += 32) {
        __syncthreads();
        for (int i = t; i < 1024; i += 256) {
            int kk = i >> 5, cq = i & 31;
            *(float4*)&ws[kk * 128 + cq * 4] = *(const float4*)&W[(size_t)(kc + kk) * 128 + cq * 4];
        }
        __syncthreads();
#pragma unroll 8
        for (int k = 0; k < 32; k++) {
            float xv = xs[rl * 132 + kc + k];
            unsigned long long xp = pack2(xv, xv);
#pragma unroll
            for (int i = 0; i < 8; i++) {
                int c = colq * 4 + i * 16;
                ulonglong2 wp = *(const ulonglong2*)&ws[k * 128 + c];
                fma2(acc[2 * i], xp, wp.x);
                fma2(acc[2 * i + 1], xp, wp.y);
            }
        }
    }

    int row = row0 + rl;
    float hv[8][4];
#pragma unroll
    for (int i = 0; i < 8; i++) {
        float2 lo = unpack2(acc[2 * i]);
        float2 hi = unpack2(acc[2 * i + 1]);
        hv[i][0] = lo.x; hv[i][1] = lo.y; hv[i][2] = hi.x; hv[i][3] = hi.y;
    }
    if (row < n) {
#pragma unroll
        for (int i = 0; i < 8; i++) {
            int c = colq * 4 + i * 16;
            *(float4*)&g_h1[(size_t)row * 128 + c] =
                make_float4(hv[i][0], hv[i][1], hv[i][2], hv[i][3]);
        }
    }
    // fused attention dots: c = 32*(i>>1) + 16*(i&1) + 4*colq + j
    float pS[4] = {0.f, 0.f, 0.f, 0.f}, pD[4] = {0.f, 0.f, 0.f, 0.f};
#pragma unroll
    for (int i = 0; i < 8; i++) {
        int h = i >> 1;
        int base = 16 * (i & 1) + 4 * colq;
#pragma unroll
        for (int j = 0; j < 4; j++) {
            pS[h] = fmaf(hv[i][j], asrc[h * 32 + base + j], pS[h]);
            pD[h] = fmaf(hv[i][j], adst[h * 32 + base + j], pD[h]);
        }
    }
#pragma unroll
    for (int step = 1; step <= 2; step <<= 1) {
#pragma unroll
        for (int h = 0; h < 4; h++) {
            pS[h] += __shfl_xor_sync(0xFFFFFFFFu, pS[h], step);
            pD[h] += __shfl_xor_sync(0xFFFFFFFFu, pD[h], step);
        }
    }
    if (colq == 0 && row < n) {
#pragma unroll
        for (int h = 0; h < 4; h++) {
            g_als1[row * 4 + h] = pS[h];
            g_ald1[row * 4 + h] = pD[h];
        }
    }
}

// ---------------- Layer-1 edge aggregation (warp per dst node) ---------------
__device__ __forceinline__ float leaky(float e) { return e > 0.f ? e : NEG_SLOPE * e; }

__global__ void k_agg1(const float* __restrict__ b1, int n) {
    int w = (blockIdx.x * blockDim.x + threadIdx.x) >> 5;
    int lane = threadIdx.x & 31;
    if (w >= n) return;
    int start = g_rowptr[w], end = g_rowptr[w + 1];
    float4 aldv = *(const float4*)&g_ald1[w * 4];
    float ald0 = aldv.x, ald1 = aldv.y, ald2 = aldv.z, ald3 = aldv.w;

    float m0 = -1e30f, m1 = -1e30f, m2 = -1e30f, m3 = -1e30f;
    for (int j = start + lane; j < end; j += 32) {
        int s = g_col[j];
        float4 as = *(const float4*)&g_als1[s * 4];
        m0 = fmaxf(m0, leaky(as.x + ald0));
        m1 = fmaxf(m1, leaky(as.y + ald1));
        m2 = fmaxf(m2, leaky(as.z + ald2));
        m3 = fmaxf(m3, leaky(as.w + ald3));
    }
#pragma unroll
    for (int off = 16; off; off >>= 1) {
        m0 = fmaxf(m0, __shfl_xor_sync(0xFFFFFFFFu, m0, off));
        m1 = fmaxf(m1, __shfl_xor_sync(0xFFFFFFFFu, m1, off));
        m2 = fmaxf(m2, __shfl_xor_sync(0xFFFFFFFFu, m2, off));
        m3 = fmaxf(m3, __shfl_xor_sync(0xFFFFFFFFu, m3, off));
    }
    float d0 = 0.f, d1 = 0.f, d2 = 0.f, d3 = 0.f;
    for (int j = start + lane; j < end; j += 32) {
        int s = g_col[j];
        float4 as = *(const float4*)&g_als1[s * 4];
        d0 += __expf(leaky(as.x + ald0) - m0);
        d1 += __expf(leaky(as.y + ald1) - m1);
        d2 += __expf(leaky(as.z + ald2) - m2);
        d3 += __expf(leaky(as.w + ald3) - m3);
    }
#pragma unroll
    for (int off = 16; off; off >>= 1) {
        d0 += __shfl_xor_sync(0xFFFFFFFFu, d0, off);
        d1 += __shfl_xor_sync(0xFFFFFFFFu, d1, off);
        d2 += __shfl_xor_sync(0xFFFFFFFFu, d2, off);
        d3 += __shfl_xor_sync(0xFFFFFFFFu, d3, off);
    }
    int h = lane >> 3;
    float mh   = (h == 0) ? m0 : (h == 1) ? m1 : (h == 2) ? m2 : m3;
    float dh   = (h == 0) ? d0 : (h == 1) ? d1 : (h == 2) ? d2 : d3;
    float aldh = (h == 0) ? ald0 : (h == 1) ? ald1 : (h == 2) ? ald2 : ald3;
    float rdh = 1.0f / dh;

    float a0 = 0.f, a1 = 0.f, a2 = 0.f, a3 = 0.f;
    int c = lane << 2;
    for (int j = start; j < end; j++) {
        int s = g_col[j];
        float alpha = __expf(leaky(g_als1[s * 4 + h] + aldh) - mh) * rdh;
        float4 hv = *(const float4*)&g_h1[(size_t)s * 128 + c];
        a0 = fmaf(hv.x, alpha, a0);
        a1 = fmaf(hv.y, alpha, a1);
        a2 = fmaf(hv.z, alpha, a2);
        a3 = fmaf(hv.w, alpha, a3);
    }
    float4 bb = *(const float4*)&b1[c];
    float4 o;
    o.x = fmaxf(a0 + bb.x, 0.f);
    o.y = fmaxf(a1 + bb.y, 0.f);
    o.z = fmaxf(a2 + bb.z, 0.f);
    o.w = fmaxf(a3 + bb.w, 0.f);
    *(float4*)&g_x2[(size_t)w * 128 + c] = o;
}

// ---------------- GEMM2: h2 = x2 @ W2 [128,16] + fused dots ------------------
__global__ void k_gemm2(const float* __restrict__ W, const float* __restrict__ asrc,
                        const float* __restrict__ adst, int n) {
    __shared__ float xs[16 * 128];
    __shared__ float ws[128 * 16];
    int t = threadIdx.x;
    int r0 = blockIdx.x * 16;
    for (int i = t; i < 128 * 16 / 4; i += 256)
        *(float4*)&ws[i * 4] = *(const float4*)&W[i * 4];
    for (int i = t; i < 16 * 128 / 4; i += 256) {
        int r = (i * 4) >> 7;
        float4 v = make_float4(0.f, 0.f, 0.f, 0.f);
        if (r0 + r < n) v = *(const float4*)&g_x2[(size_t)r0 * 128 + i * 4];
        *(float4*)&xs[i * 4] = v;
    }
    __syncthreads();
    int row = t >> 4, c = t & 15;
    float acc = 0.f;
#pragma unroll 8
    for (int k = 0; k < 128; k++) acc = fmaf(xs[row * 128 + k], ws[k * 16 + c], acc);
    int grow = r0 + row;
    if (grow < n) g_h2[grow * 16 + c] = acc;
    float pS = acc * asrc[c];
    float pD = acc * adst[c];
#pragma unroll
    for (int step = 1; step < 16; step <<= 1) {
        pS += __shfl_xor_sync(0xFFFFFFFFu, pS, step);
        pD += __shfl_xor_sync(0xFFFFFFFFu, pD, step);
    }
    if (c == 0 && grow < n) {
        g_als2[grow] = pS;
        g_ald2[grow] = pD;
    }
}

// ---------------- Layer-2 edge aggregation (warp per dst node) ---------------
__global__ void k_agg2(const float* __restrict__ b2, float* __restrict__ out, int n) {
    int w = (blockIdx.x * blockDim.x + threadIdx.x) >> 5;
    int lane = threadIdx.x & 31;
    if (w >= n) return;
    int start = g_rowptr[w], end = g_rowptr[w + 1];
    float ald = g_ald2[w];
    float m = -1e30f;
    for (int j = start + lane; j < end; j += 32)
        m = fmaxf(m, leaky(g_als2[g_col[j]] + ald));
#pragma unroll
    for (int off = 16; off; off >>= 1) m = fmaxf(m, __shfl_xor_sync(0xFFFFFFFFu, m, off));
    float d = 0.f;
    for (int j = start + lane; j < end; j += 32)
        d += __expf(leaky(g_als2[g_col[j]] + ald) - m);
#pragma unroll
    for (int off = 16; off; off >>= 1) d += __shfl_xor_sync(0xFFFFFFFFu, d, off);
    float rd = 1.0f / d;

    int half = lane >> 4, c = lane & 15;
    float acc = 0.f;
    for (int j = start + half; j < end; j += 2) {
        int s = g_col[j];
        float alpha = __expf(leaky(g_als2[s] + ald) - m) * rd;
        acc = fmaf(g_h2[s * 16 + c], alpha, acc);
    }
    acc += __shfl_xor_sync(0xFFFFFFFFu, acc, 16);
    if (half == 0) out[(size_t)w * 16 + c] = acc + b2[c];
}

// ---------------- launch -----------------------------------------------------
extern "C" void kernel_launch(void* const* d_in, const int* in_sizes, int n_in,
                              void* d_out, int out_size) {
    const float* x = (const float*)d_in[0];
    const void* ei = d_in[1];
    const float* W1 = (const float*)d_in[2];
    const float* as1 = (const float*)d_in[3];
    const float* ad1 = (const float*)d_in[4];
    const float* b1 = (const float*)d_in[5];
    const float* W2 = (const float*)d_in[6];
    const float* as2 = (const float*)d_in[7];
    const float* ad2 = (const float*)d_in[8];
    const float* b2 = (const float*)d_in[9];
    float* out = (float*)d_out;

    int N = in_sizes[0] / 128;
    int E = in_sizes[1] / 2;
    if (N > MAXN) N = MAXN;
    if (E > MAXE) E = MAXE;

    // dtype probe + edge normalization (handles int32 or int64 edge_index)
    k_probe<<<1, 32>>>((const int*)ei, E);
    k_convert<<<(E + 255) / 256, 256>>>(ei, E, N);

    // CSR build (dst-indexed, includes self loops)
    k_deg_init<<<(N + 255) / 256, 256>>>(N);
    k_deg_count<<<(E + 255) / 256, 256>>>(E);
    k_scan<<<1, 1024>>>(N);
    k_self<<<(N + 255) / 256, 256>>>(N);
    k_fill<<<(E + 255) / 256, 256>>>(E);

    // layer 1
    k_gemm1<<<(N + 63) / 64, 256>>>(x, W1, as1, ad1, N);
    k_agg1<<<(N + 7) / 8, 256>>>(b1, N);
    // layer 2
    k_gemm2<<<(N + 15) / 16, 256>>>(W2, as2, ad2, N);
    k_agg2<<<(N + 7) / 8, 256>>>(b2, out, N);
}

// round 5
// speedup vs baseline: 1.0888x; 1.0888x over previous
#include <cuda_runtime.h>

#define MAXN 100000
#define MAXE 1600000
#define MAXTOT (MAXN + MAXE)
#define NEG_SLOPE 0.2f

// ---------------- scratch ---------------------------------------------------
__device__ __align__(16) float g_h1[MAXN * 128];
__device__ __align__(16) float g_als1[MAXN * 4];
__device__ __align__(16) float g_ald1[MAXN * 4];
__device__ __align__(16) float g_x2[MAXN * 128];
__device__ __align__(16) float g_h2[MAXN * 16];
__device__ float g_als2[MAXN];
__device__ float g_ald2[MAXN];
__device__ int g_deg[MAXN];
__device__ int g_rowptr[MAXN + 1];
__device__ int g_cursor[MAXN];
__device__ int g_col[MAXTOT];
__device__ int g_src[MAXE];
__device__ int g_dst[MAXE];
__device__ int g_is64;

// ---------------- f32x2 helpers ---------------------------------------------
__device__ __forceinline__ unsigned long long pack2(float a, float b) {
    unsigned long long r;
    asm("mov.b64 %0, {%1, %2};" : "=l"(r) : "f"(a), "f"(b));
    return r;
}
__device__ __forceinline__ void fma2(unsigned long long& d, unsigned long long a,
                                     unsigned long long b) {
    asm("fma.rn.f32x2 %0, %1, %2, %0;" : "+l"(d) : "l"(a), "l"(b));
}
__device__ __forceinline__ float2 unpack2(unsigned long long v) {
    float2 f;
    asm("mov.b64 {%0, %1}, %2;" : "=f"(f.x), "=f"(f.y) : "l"(v));
    return f;
}

__device__ __forceinline__ float leaky(float e) { return e > 0.f ? e : NEG_SLOPE * e; }

// ---------------- edge-index probe / normalize / count -----------------------
__global__ void k_probe(const int* __restrict__ ei32, int E) {
    if (threadIdx.x == 0 && blockIdx.x == 0) {
        int cnt = E < 64 ? E : 64;
        int zeros = 0;
        for (int i = 0; i < cnt; i++) zeros += (ei32[2 * i + 1] == 0) ? 1 : 0;
        g_is64 = (zeros == cnt) ? 1 : 0;
    }
}

__global__ void k_zero_deg(int n) {
    int i = blockIdx.x * blockDim.x + threadIdx.x;
    if (i < n) g_deg[i] = 0;
}

// convert + degree count fused
__global__ void k_convert(const void* __restrict__ ei, int E, int N) {
    int e = blockIdx.x * blockDim.x + threadIdx.x;
    if (e >= E) return;
    int s, d;
    if (g_is64) {
        const long long* p = (const long long*)ei;
        s = (int)p[e];
        d = (int)p[E + e];
    } else {
        const int* p = (const int*)ei;
        s = p[e];
        d = p[E + e];
    }
    s = min(max(s, 0), N - 1);
    d = min(max(d, 0), N - 1);
    g_src[e] = s;
    g_dst[e] = d;
    atomicAdd(&g_deg[d], 1);
}

// scan over (deg+1), write rowptr, insert self-loop col, set cursor past it
__global__ void k_scan(int n) {
    __shared__ int ssum[1024];
    int t = threadIdx.x;
    int chunk = (n + 1023) / 1024;
    int b = t * chunk; if (b > n) b = n;
    int e = b + chunk; if (e > n) e = n;
    int s = 0;
    for (int i = b; i < e; i++) s += g_deg[i] + 1;
    ssum[t] = s;
    __syncthreads();
    for (int off = 1; off < 1024; off <<= 1) {
        int v = (t >= off) ? ssum[t - off] : 0;
        __syncthreads();
        ssum[t] += v;
        __syncthreads();
    }
    int run = ssum[t] - s;
    for (int i = b; i < e; i++) {
        g_rowptr[i] = run;
        g_col[run] = i;          // self loop occupies first slot
        g_cursor[i] = run + 1;
        run += g_deg[i] + 1;
    }
    if (t == 1023) g_rowptr[n] = ssum[1023];
}

__global__ void k_fill(int E) {
    int e = blockIdx.x * blockDim.x + threadIdx.x;
    if (e < E) {
        int pos = atomicAdd(&g_cursor[g_dst[e]], 1);
        g_col[pos] = g_src[e];
    }
}

// ---------------- GEMM1: 128x128 tile, 8x8 per-thread register blocking ------
__global__ void k_gemm1(const float* __restrict__ x, const float* __restrict__ W,
                        const float* __restrict__ asrc, const float* __restrict__ adst,
                        int n) {
    __shared__ float xs[128 * 33];   // [row][k], stride 33 (bank-safe)
    __shared__ float ws[32 * 128];   // [k][col]
    int t = threadIdx.x;
    int tx = t & 15, ty = t >> 4;
    int row0 = blockIdx.x * 128;

    unsigned long long acc[8][4];
#pragma unroll
    for (int i = 0; i < 8; i++)
#pragma unroll
        for (int j = 0; j < 4; j++) acc[i][j] = pack2(0.f, 0.f);

    for (int kc = 0; kc < 128; kc += 32) {
        // load x tile: 128 rows x 32 k
        for (int i = t; i < 1024; i += 256) {
            int r = i >> 3, cq = i & 7;
            float4 v = make_float4(0.f, 0.f, 0.f, 0.f);
            if (row0 + r < n)
                v = *(const float4*)&x[(size_t)(row0 + r) * 128 + kc + cq * 4];
            float* p = &xs[r * 33 + cq * 4];
            p[0] = v.x; p[1] = v.y; p[2] = v.z; p[3] = v.w;
        }
        // load W tile: rows kc..kc+31, all 128 cols (contiguous)
        for (int i = t; i < 1024; i += 256)
            *(float4*)&ws[i * 4] = *(const float4*)&W[(size_t)kc * 128 + i * 4];
        __syncthreads();
#pragma unroll 4
        for (int k = 0; k < 32; k++) {
            float4 wa = *(const float4*)&ws[k * 128 + tx * 8];
            float4 wb = *(const float4*)&ws[k * 128 + tx * 8 + 4];
            unsigned long long wp0 = pack2(wa.x, wa.y);
            unsigned long long wp1 = pack2(wa.z, wa.w);
            unsigned long long wp2 = pack2(wb.x, wb.y);
            unsigned long long wp3 = pack2(wb.z, wb.w);
#pragma unroll
            for (int i = 0; i < 8; i++) {
                float xv = xs[(ty * 8 + i) * 33 + k];
                unsigned long long xp = pack2(xv, xv);
                fma2(acc[i][0], xp, wp0);
                fma2(acc[i][1], xp, wp1);
                fma2(acc[i][2], xp, wp2);
                fma2(acc[i][3], xp, wp3);
            }
        }
        __syncthreads();
    }

    // epilogue: store h1 + fused attention dots
    int h0 = tx >> 2;              // head of this thread's 8 cols
    int base = (tx & 3) * 8;       // within-head col offset
    float aS[8], aD[8];
#pragma unroll
    for (int j = 0; j < 8; j++) {
        aS[j] = asrc[h0 * 32 + base + j];
        aD[j] = adst[h0 * 32 + base + j];
    }
#pragma unroll
    for (int i = 0; i < 8; i++) {
        int row = row0 + ty * 8 + i;
        float2 p0 = unpack2(acc[i][0]);
        float2 p1 = unpack2(acc[i][1]);
        float2 p2 = unpack2(acc[i][2]);
        float2 p3 = unpack2(acc[i][3]);
        float hv[8] = {p0.x, p0.y, p1.x, p1.y, p2.x, p2.y, p3.x, p3.y};
        if (row < n) {
            *(float4*)&g_h1[(size_t)row * 128 + tx * 8] =
                make_float4(hv[0], hv[1], hv[2], hv[3]);
            *(float4*)&g_h1[(size_t)row * 128 + tx * 8 + 4] =
                make_float4(hv[4], hv[5], hv[6], hv[7]);
        }
        float pS = 0.f, pD = 0.f;
#pragma unroll
        for (int j = 0; j < 8; j++) {
            pS = fmaf(hv[j], aS[j], pS);
            pD = fmaf(hv[j], aD[j], pD);
        }
        // reduce over tx&3 (lane bits 0,1)
        pS += __shfl_xor_sync(0xFFFFFFFFu, pS, 1);
        pD += __shfl_xor_sync(0xFFFFFFFFu, pD, 1);
        pS += __shfl_xor_sync(0xFFFFFFFFu, pS, 2);
        pD += __shfl_xor_sync(0xFFFFFFFFu, pD, 2);
        if ((tx & 3) == 0 && row < n) {
            g_als1[row * 4 + h0] = pS;
            g_ald1[row * 4 + h0] = pD;
        }
    }
}

// ---------------- Layer-1 aggregation: warp per dst, batched gather ----------
__global__ void k_agg1(const float* __restrict__ b1, int n) {
    int w = (blockIdx.x * blockDim.x + threadIdx.x) >> 5;
    int lane = threadIdx.x & 31;
    if (w >= n) return;
    int start = g_rowptr[w], end = g_rowptr[w + 1];
    float4 aldv = *(const float4*)&g_ald1[w * 4];

    // fused max + denom with 4-stride register cache of logits
    float vc[4][4];
    float m0 = -1e30f, m1 = -1e30f, m2 = -1e30f, m3 = -1e30f;
    int nit = 0;
    for (int jb = start; jb < end; jb += 32, nit++) {
        int j = jb + lane;
        float v0 = -1e30f, v1 = -1e30f, v2 = -1e30f, v3 = -1e30f;
        if (j < end) {
            int s = g_col[j];
            float4 as = *(const float4*)&g_als1[s * 4];
            v0 = leaky(as.x + aldv.x);
            v1 = leaky(as.y + aldv.y);
            v2 = leaky(as.z + aldv.z);
            v3 = leaky(as.w + aldv.w);
        }
        if (nit < 4) { vc[nit][0] = v0; vc[nit][1] = v1; vc[nit][2] = v2; vc[nit][3] = v3; }
        m0 = fmaxf(m0, v0); m1 = fmaxf(m1, v1);
        m2 = fmaxf(m2, v2); m3 = fmaxf(m3, v3);
    }
#pragma unroll
    for (int off = 16; off; off >>= 1) {
        m0 = fmaxf(m0, __shfl_xor_sync(0xFFFFFFFFu, m0, off));
        m1 = fmaxf(m1, __shfl_xor_sync(0xFFFFFFFFu, m1, off));
        m2 = fmaxf(m2, __shfl_xor_sync(0xFFFFFFFFu, m2, off));
        m3 = fmaxf(m3, __shfl_xor_sync(0xFFFFFFFFu, m3, off));
    }
    float d0 = 0.f, d1 = 0.f, d2 = 0.f, d3 = 0.f;
    nit = 0;
    for (int jb = start; jb < end; jb += 32, nit++) {
        float v0, v1, v2, v3;
        if (nit < 4) {
            v0 = vc[nit][0]; v1 = vc[nit][1]; v2 = vc[nit][2]; v3 = vc[nit][3];
        } else {
            int j = jb + lane;
            v0 = v1 = v2 = v3 = -1e30f;
            if (j < end) {
                int s = g_col[j];
                float4 as = *(const float4*)&g_als1[s * 4];
                v0 = leaky(as.x + aldv.x);
                v1 = leaky(as.y + aldv.y);
                v2 = leaky(as.z + aldv.z);
                v3 = leaky(as.w + aldv.w);
            }
        }
        d0 += __expf(v0 - m0);
        d1 += __expf(v1 - m1);
        d2 += __expf(v2 - m2);
        d3 += __expf(v3 - m3);
    }
#pragma unroll
    for (int off = 16; off; off >>= 1) {
        d0 += __shfl_xor_sync(0xFFFFFFFFu, d0, off);
        d1 += __shfl_xor_sync(0xFFFFFFFFu, d1, off);
        d2 += __shfl_xor_sync(0xFFFFFFFFu, d2, off);
        d3 += __shfl_xor_sync(0xFFFFFFFFu, d3, off);
    }
    int h = lane >> 3;
    float mh   = (h == 0) ? m0 : (h == 1) ? m1 : (h == 2) ? m2 : m3;
    float dh   = (h == 0) ? d0 : (h == 1) ? d1 : (h == 2) ? d2 : d3;
    float aldh = (h == 0) ? aldv.x : (h == 1) ? aldv.y : (h == 2) ? aldv.z : aldv.w;
    float rdh = 1.0f / dh;

    // weighted gather: batches of 8 edges, alphas precomputed per (edge, head)
    float a0 = 0.f, a1 = 0.f, a2 = 0.f, a3 = 0.f;
    int c = lane << 2;
    int asel = lane & 24;
    for (int jb = start; jb < end; jb += 8) {
        int j = jb + (lane & 7);
        int scol = 0;
        float alpha = 0.f;
        if (j < end) {
            scol = g_col[j];
            alpha = __expf(leaky(g_als1[scol * 4 + h] + aldh) - mh) * rdh;
        }
        int cnt = min(8, end - jb);
        if (cnt == 8) {
#pragma unroll
            for (int u = 0; u < 8; u++) {
                int s = __shfl_sync(0xFFFFFFFFu, scol, u);
                float a = __shfl_sync(0xFFFFFFFFu, alpha, asel | u);
                float4 hv = *(const float4*)&g_h1[(size_t)s * 128 + c];
                a0 = fmaf(hv.x, a, a0);
                a1 = fmaf(hv.y, a, a1);
                a2 = fmaf(hv.z, a, a2);
                a3 = fmaf(hv.w, a, a3);
            }
        } else {
            for (int u = 0; u < cnt; u++) {
                int s = __shfl_sync(0xFFFFFFFFu, scol, u);
                float a = __shfl_sync(0xFFFFFFFFu, alpha, asel | u);
                float4 hv = *(const float4*)&g_h1[(size_t)s * 128 + c];
                a0 = fmaf(hv.x, a, a0);
                a1 = fmaf(hv.y, a, a1);
                a2 = fmaf(hv.z, a, a2);
                a3 = fmaf(hv.w, a, a3);
            }
        }
    }
    float4 bb = *(const float4*)&b1[c];
    float4 o;
    o.x = fmaxf(a0 + bb.x, 0.f);
    o.y = fmaxf(a1 + bb.y, 0.f);
    o.z = fmaxf(a2 + bb.z, 0.f);
    o.w = fmaxf(a3 + bb.w, 0.f);
    *(float4*)&g_x2[(size_t)w * 128 + c] = o;
}

// ---------------- GEMM2: h2 = x2 @ W2 [128,16] + fused dots ------------------
__global__ void k_gemm2(const float* __restrict__ W, const float* __restrict__ asrc,
                        const float* __restrict__ adst, int n) {
    __shared__ float xs[16 * 128];
    __shared__ float ws[128 * 16];
    int t = threadIdx.x;
    int r0 = blockIdx.x * 16;
    for (int i = t; i < 128 * 16 / 4; i += 256)
        *(float4*)&ws[i * 4] = *(const float4*)&W[i * 4];
    for (int i = t; i < 16 * 128 / 4; i += 256) {
        int r = (i * 4) >> 7;
        float4 v = make_float4(0.f, 0.f, 0.f, 0.f);
        if (r0 + r < n) v = *(const float4*)&g_x2[(size_t)r0 * 128 + i * 4];
        *(float4*)&xs[i * 4] = v;
    }
    __syncthreads();
    int row = t >> 4, c = t & 15;
    float acc = 0.f;
#pragma unroll 8
    for (int k = 0; k < 128; k++) acc = fmaf(xs[row * 128 + k], ws[k * 16 + c], acc);
    int grow = r0 + row;
    if (grow < n) g_h2[grow * 16 + c] = acc;
    float pS = acc * asrc[c];
    float pD = acc * adst[c];
#pragma unroll
    for (int step = 1; step < 16; step <<= 1) {
        pS += __shfl_xor_sync(0xFFFFFFFFu, pS, step);
        pD += __shfl_xor_sync(0xFFFFFFFFu, pD, step);
    }
    if (c == 0 && grow < n) {
        g_als2[grow] = pS;
        g_ald2[grow] = pD;
    }
}

// ---------------- Layer-2 aggregation ----------------------------------------
__global__ void k_agg2(const float* __restrict__ b2, float* __restrict__ out, int n) {
    int w = (blockIdx.x * blockDim.x + threadIdx.x) >> 5;
    int lane = threadIdx.x & 31;
    if (w >= n) return;
    int start = g_rowptr[w], end = g_rowptr[w + 1];
    float ald = g_ald2[w];

    float vcc[4];
    float m = -1e30f;
    int nit = 0;
    for (int jb = start; jb < end; jb += 32, nit++) {
        int j = jb + lane;
        float v = -1e30f;
        if (j < end) v = leaky(g_als2[g_col[j]] + ald);
        if (nit < 4) vcc[nit] = v;
        m = fmaxf(m, v);
    }
#pragma unroll
    for (int off = 16; off; off >>= 1) m = fmaxf(m, __shfl_xor_sync(0xFFFFFFFFu, m, off));
    float d = 0.f;
    nit = 0;
    for (int jb = start; jb < end; jb += 32, nit++) {
        float v;
        if (nit < 4) v = vcc[nit];
        else {
            int j = jb + lane;
            v = -1e30f;
            if (j < end) v = leaky(g_als2[g_col[j]] + ald);
        }
        d += __expf(v - m);
    }
#pragma unroll
    for (int off = 16; off; off >>= 1) d += __shfl_xor_sync(0xFFFFFFFFu, d, off);
    float rd = 1.0f / d;

    // batched gather: warp-uniform loop; each half-warp takes alternate edges.
    // shfl source lane varies per lane (legal); loop structure is convergent.
    int half = lane >> 4, c = lane & 15;
    float acc = 0.f;
    for (int jb = start; jb < end; jb += 32) {
        int j = jb + lane;
        int scol = 0;
        float alpha = 0.f;
        if (j < end) {
            scol = g_col[j];
            alpha = __expf(leaky(g_als2[scol] + ald) - m) * rd;
        }
        int cnt = min(32, end - jb);
        for (int u = 0; u < cnt; u += 2) {
            int uu = u + half;                 // this half-warp's edge slot
            int su = uu < cnt ? uu : 0;
            int s = __shfl_sync(0xFFFFFFFFu, scol, su);
            float a = __shfl_sync(0xFFFFFFFFu, alpha, su);
            if (uu < cnt) acc = fmaf(g_h2[s * 16 + c], a, acc);
        }
    }
    acc += __shfl_xor_sync(0xFFFFFFFFu, acc, 16);
    if (half == 0) out[(size_t)w * 16 + c] = acc + b2[c];
}

// ---------------- launch -----------------------------------------------------
extern "C" void kernel_launch(void* const* d_in, const int* in_sizes, int n_in,
                              void* d_out, int out_size) {
    const float* x = (const float*)d_in[0];
    const void* ei = d_in[1];
    const float* W1 = (const float*)d_in[2];
    const float* as1 = (const float*)d_in[3];
    const float* ad1 = (const float*)d_in[4];
    const float* b1 = (const float*)d_in[5];
    const float* W2 = (const float*)d_in[6];
    const float* as2 = (const float*)d_in[7];
    const float* ad2 = (const float*)d_in[8];
    const float* b2 = (const float*)d_in[9];
    float* out = (float*)d_out;

    int N = in_sizes[0] / 128;
    int E = in_sizes[1] / 2;
    if (N > MAXN) N = MAXN;
    if (E > MAXE) E = MAXE;

    k_probe<<<1, 32>>>((const int*)ei, E);
    k_zero_deg<<<(N + 255) / 256, 256>>>(N);
    k_convert<<<(E + 255) / 256, 256>>>(ei, E, N);
    k_scan<<<1, 1024>>>(N);
    k_fill<<<(E + 255) / 256, 256>>>(E);

    k_gemm1<<<(N + 127) / 128, 256>>>(x, W1, as1, ad1, N);
    k_agg1<<<(N + 7) / 8, 256>>>(b1, N);
    k_gemm2<<<(N + 15) / 16, 256>>>(W2, as2, ad2, N);
    k_agg2<<<(N + 7) / 8, 256>>>(b2, out, N);
}

// round 7
// speedup vs baseline: 1.2198x; 1.1204x over previous
#include <cuda_runtime.h>

#define MAXN 100000
#define MAXE 1600000
#define MAXTOT (MAXN + MAXE)
#define NEG_SLOPE 0.2f

// ---------------- scratch ---------------------------------------------------
__device__ __align__(16) float g_h1[MAXN * 128];
__device__ __align__(16) float g_als1[MAXN * 4];
__device__ __align__(16) float g_ald1[MAXN * 4];
__device__ __align__(16) float g_x2[MAXN * 128];
__device__ __align__(16) float g_h2[MAXN * 16];
__device__ float g_als2[MAXN];
__device__ float g_ald2[MAXN];
__device__ int g_deg[MAXN];
__device__ int g_rowptr[MAXN];     // row START only (order-free allocation)
__device__ int g_cursor[MAXN];
__device__ int g_col[MAXTOT];
__device__ int g_src[MAXE];
__device__ int g_dst[MAXE];
__device__ int g_is64;
__device__ int g_total;

// ---------------- f32x2 helpers ---------------------------------------------
__device__ __forceinline__ unsigned long long pack2(float a, float b) {
    unsigned long long r;
    asm("mov.b64 %0, {%1, %2};" : "=l"(r) : "f"(a), "f"(b));
    return r;
}
__device__ __forceinline__ void fma2(unsigned long long& d, unsigned long long a,
                                     unsigned long long b) {
    asm("fma.rn.f32x2 %0, %1, %2, %0;" : "+l"(d) : "l"(a), "l"(b));
}
__device__ __forceinline__ float2 unpack2(unsigned long long v) {
    float2 f;
    asm("mov.b64 {%0, %1}, %2;" : "=f"(f.x), "=f"(f.y) : "l"(v));
    return f;
}

__device__ __forceinline__ float leaky(float e) { return e > 0.f ? e : NEG_SLOPE * e; }

// ---------------- edge-index probe / normalize / count -----------------------
__global__ void k_probe(const int* __restrict__ ei32, int E) {
    if (threadIdx.x == 0 && blockIdx.x == 0) {
        int cnt = E < 64 ? E : 64;
        int zeros = 0;
        for (int i = 0; i < cnt; i++) zeros += (ei32[2 * i + 1] == 0) ? 1 : 0;
        g_is64 = (zeros == cnt) ? 1 : 0;
        g_total = 0;
    }
}

__global__ void k_zero_deg(int n) {
    int i = blockIdx.x * blockDim.x + threadIdx.x;
    if (i < n) g_deg[i] = 0;
}

// convert + degree count fused
__global__ void k_convert(const void* __restrict__ ei, int E, int N) {
    int e = blockIdx.x * blockDim.x + threadIdx.x;
    if (e >= E) return;
    int s, d;
    if (g_is64) {
        const long long* p = (const long long*)ei;
        s = (int)p[e];
        d = (int)p[E + e];
    } else {
        const int* p = (const int*)ei;
        s = p[e];
        d = p[E + e];
    }
    s = min(max(s, 0), N - 1);
    d = min(max(d, 0), N - 1);
    g_src[e] = s;
    g_dst[e] = d;
    atomicAdd(&g_deg[d], 1);
}

// parallel segment allocator: CSR row order is irrelevant, so skip the global
// prefix sum. Warp-scan (deg+1), one atomicAdd per warp, write row start,
// plant self-loop in slot 0, point cursor past it.
__global__ void k_alloc(int n) {
    int i = blockIdx.x * blockDim.x + threadIdx.x;
    int lane = threadIdx.x & 31;
    int v = (i < n) ? g_deg[i] + 1 : 0;
    int incl = v;
#pragma unroll
    for (int off = 1; off < 32; off <<= 1) {
        int t = __shfl_up_sync(0xFFFFFFFFu, incl, off);
        if (lane >= off) incl += t;
    }
    int tot = __shfl_sync(0xFFFFFFFFu, incl, 31);
    int base = 0;
    if (lane == 0) base = atomicAdd(&g_total, tot);
    base = __shfl_sync(0xFFFFFFFFu, base, 0);
    int pos = base + incl - v;
    if (i < n) {
        g_rowptr[i] = pos;
        g_col[pos] = i;          // self loop occupies first slot
        g_cursor[i] = pos + 1;
    }
}

__global__ void k_fill(int E) {
    int e = blockIdx.x * blockDim.x + threadIdx.x;
    if (e < E) {
        int pos = atomicAdd(&g_cursor[g_dst[e]], 1);
        g_col[pos] = g_src[e];
    }
}

// ---------------- GEMM1: 128x128 tile, 8x8 per-thread register blocking ------
__global__ void k_gemm1(const float* __restrict__ x, const float* __restrict__ W,
                        const float* __restrict__ asrc, const float* __restrict__ adst,
                        int n) {
    __shared__ float xs[128 * 33];   // [row][k], stride 33 (bank-safe)
    __shared__ float ws[32 * 128];   // [k][col]
    int t = threadIdx.x;
    int tx = t & 15, ty = t >> 4;
    int row0 = blockIdx.x * 128;

    unsigned long long acc[8][4];
#pragma unroll
    for (int i = 0; i < 8; i++)
#pragma unroll
        for (int j = 0; j < 4; j++) acc[i][j] = pack2(0.f, 0.f);

    for (int kc = 0; kc < 128; kc += 32) {
        for (int i = t; i < 1024; i += 256) {
            int r = i >> 3, cq = i & 7;
            float4 v = make_float4(0.f, 0.f, 0.f, 0.f);
            if (row0 + r < n)
                v = *(const float4*)&x[(size_t)(row0 + r) * 128 + kc + cq * 4];
            float* p = &xs[r * 33 + cq * 4];
            p[0] = v.x; p[1] = v.y; p[2] = v.z; p[3] = v.w;
        }
        for (int i = t; i < 1024; i += 256)
            *(float4*)&ws[i * 4] = *(const float4*)&W[(size_t)kc * 128 + i * 4];
        __syncthreads();
#pragma unroll 4
        for (int k = 0; k < 32; k++) {
            float4 wa = *(const float4*)&ws[k * 128 + tx * 8];
            float4 wb = *(const float4*)&ws[k * 128 + tx * 8 + 4];
            unsigned long long wp0 = pack2(wa.x, wa.y);
            unsigned long long wp1 = pack2(wa.z, wa.w);
            unsigned long long wp2 = pack2(wb.x, wb.y);
            unsigned long long wp3 = pack2(wb.z, wb.w);
#pragma unroll
            for (int i = 0; i < 8; i++) {
                float xv = xs[(ty * 8 + i) * 33 + k];
                unsigned long long xp = pack2(xv, xv);
                fma2(acc[i][0], xp, wp0);
                fma2(acc[i][1], xp, wp1);
                fma2(acc[i][2], xp, wp2);
                fma2(acc[i][3], xp, wp3);
            }
        }
        __syncthreads();
    }

    int h0 = tx >> 2;
    int base = (tx & 3) * 8;
    float aS[8], aD[8];
#pragma unroll
    for (int j = 0; j < 8; j++) {
        aS[j] = asrc[h0 * 32 + base + j];
        aD[j] = adst[h0 * 32 + base + j];
    }
#pragma unroll
    for (int i = 0; i < 8; i++) {
        int row = row0 + ty * 8 + i;
        float2 p0 = unpack2(acc[i][0]);
        float2 p1 = unpack2(acc[i][1]);
        float2 p2 = unpack2(acc[i][2]);
        float2 p3 = unpack2(acc[i][3]);
        float hv[8] = {p0.x, p0.y, p1.x, p1.y, p2.x, p2.y, p3.x, p3.y};
        if (row < n) {
            *(float4*)&g_h1[(size_t)row * 128 + tx * 8] =
                make_float4(hv[0], hv[1], hv[2], hv[3]);
            *(float4*)&g_h1[(size_t)row * 128 + tx * 8 + 4] =
                make_float4(hv[4], hv[5], hv[6], hv[7]);
        }
        float pS = 0.f, pD = 0.f;
#pragma unroll
        for (int j = 0; j < 8; j++) {
            pS = fmaf(hv[j], aS[j], pS);
            pD = fmaf(hv[j], aD[j], pD);
        }
        pS += __shfl_xor_sync(0xFFFFFFFFu, pS, 1);
        pD += __shfl_xor_sync(0xFFFFFFFFu, pD, 1);
        pS += __shfl_xor_sync(0xFFFFFFFFu, pS, 2);
        pD += __shfl_xor_sync(0xFFFFFFFFu, pD, 2);
        if ((tx & 3) == 0 && row < n) {
            g_als1[row * 4 + h0] = pS;
            g_ald1[row * 4 + h0] = pD;
        }
    }
}

// ---------------- Layer-1 aggregation: warp per dst, batched gather ----------
__global__ void k_agg1(const float* __restrict__ b1, int n) {
    int w = (blockIdx.x * blockDim.x + threadIdx.x) >> 5;
    int lane = threadIdx.x & 31;
    if (w >= n) return;
    int start = g_rowptr[w];
    int end = start + g_deg[w] + 1;
    float4 aldv = *(const float4*)&g_ald1[w * 4];

    float vc[4][4];
    float m0 = -1e30f, m1 = -1e30f, m2 = -1e30f, m3 = -1e30f;
    int nit = 0;
    for (int jb = start; jb < end; jb += 32, nit++) {
        int j = jb + lane;
        float v0 = -1e30f, v1 = -1e30f, v2 = -1e30f, v3 = -1e30f;
        if (j < end) {
            int s = g_col[j];
            float4 as = *(const float4*)&g_als1[s * 4];
            v0 = leaky(as.x + aldv.x);
            v1 = leaky(as.y + aldv.y);
            v2 = leaky(as.z + aldv.z);
            v3 = leaky(as.w + aldv.w);
        }
        if (nit < 4) { vc[nit][0] = v0; vc[nit][1] = v1; vc[nit][2] = v2; vc[nit][3] = v3; }
        m0 = fmaxf(m0, v0); m1 = fmaxf(m1, v1);
        m2 = fmaxf(m2, v2); m3 = fmaxf(m3, v3);
    }
#pragma unroll
    for (int off = 16; off; off >>= 1) {
        m0 = fmaxf(m0, __shfl_xor_sync(0xFFFFFFFFu, m0, off));
        m1 = fmaxf(m1, __shfl_xor_sync(0xFFFFFFFFu, m1, off));
        m2 = fmaxf(m2, __shfl_xor_sync(0xFFFFFFFFu, m2, off));
        m3 = fmaxf(m3, __shfl_xor_sync(0xFFFFFFFFu, m3, off));
    }
    float d0 = 0.f, d1 = 0.f, d2 = 0.f, d3 = 0.f;
    nit = 0;
    for (int jb = start; jb < end; jb += 32, nit++) {
        float v0, v1, v2, v3;
        if (nit < 4) {
            v0 = vc[nit][0]; v1 = vc[nit][1]; v2 = vc[nit][2]; v3 = vc[nit][3];
        } else {
            int j = jb + lane;
            v0 = v1 = v2 = v3 = -1e30f;
            if (j < end) {
                int s = g_col[j];
                float4 as = *(const float4*)&g_als1[s * 4];
                v0 = leaky(as.x + aldv.x);
                v1 = leaky(as.y + aldv.y);
                v2 = leaky(as.z + aldv.z);
                v3 = leaky(as.w + aldv.w);
            }
        }
        d0 += __expf(v0 - m0);
        d1 += __expf(v1 - m1);
        d2 += __expf(v2 - m2);
        d3 += __expf(v3 - m3);
    }
#pragma unroll
    for (int off = 16; off; off >>= 1) {
        d0 += __shfl_xor_sync(0xFFFFFFFFu, d0, off);
        d1 += __shfl_xor_sync(0xFFFFFFFFu, d1, off);
        d2 += __shfl_xor_sync(0xFFFFFFFFu, d2, off);
        d3 += __shfl_xor_sync(0xFFFFFFFFu, d3, off);
    }
    int h = lane >> 3;
    float mh   = (h == 0) ? m0 : (h == 1) ? m1 : (h == 2) ? m2 : m3;
    float dh   = (h == 0) ? d0 : (h == 1) ? d1 : (h == 2) ? d2 : d3;
    float aldh = (h == 0) ? aldv.x : (h == 1) ? aldv.y : (h == 2) ? aldv.z : aldv.w;
    float rdh = 1.0f / dh;

    float a0 = 0.f, a1 = 0.f, a2 = 0.f, a3 = 0.f;
    int c = lane << 2;
    int asel = lane & 24;
    for (int jb = start; jb < end; jb += 8) {
        int j = jb + (lane & 7);
        int scol = 0;
        float alpha = 0.f;
        if (j < end) {
            scol = g_col[j];
            alpha = __expf(leaky(g_als1[scol * 4 + h] + aldh) - mh) * rdh;
        }
        int cnt = min(8, end - jb);
        if (cnt == 8) {
#pragma unroll
            for (int u = 0; u < 8; u++) {
                int s = __shfl_sync(0xFFFFFFFFu, scol, u);
                float a = __shfl_sync(0xFFFFFFFFu, alpha, asel | u);
                float4 hv = *(const float4*)&g_h1[(size_t)s * 128 + c];
                a0 = fmaf(hv.x, a, a0);
                a1 = fmaf(hv.y, a, a1);
                a2 = fmaf(hv.z, a, a2);
                a3 = fmaf(hv.w, a, a3);
            }
        } else {
            for (int u = 0; u < cnt; u++) {
                int s = __shfl_sync(0xFFFFFFFFu, scol, u);
                float a = __shfl_sync(0xFFFFFFFFu, alpha, asel | u);
                float4 hv = *(const float4*)&g_h1[(size_t)s * 128 + c];
                a0 = fmaf(hv.x, a, a0);
                a1 = fmaf(hv.y, a, a1);
                a2 = fmaf(hv.z, a, a2);
                a3 = fmaf(hv.w, a, a3);
            }
        }
    }
    float4 bb = *(const float4*)&b1[c];
    float4 o;
    o.x = fmaxf(a0 + bb.x, 0.f);
    o.y = fmaxf(a1 + bb.y, 0.f);
    o.z = fmaxf(a2 + bb.z, 0.f);
    o.w = fmaxf(a3 + bb.w, 0.f);
    *(float4*)&g_x2[(size_t)w * 128 + c] = o;
}

// ---------------- GEMM2: h2 = x2 @ W2 [128,16] + fused dots ------------------
__global__ void k_gemm2(const float* __restrict__ W, const float* __restrict__ asrc,
                        const float* __restrict__ adst, int n) {
    __shared__ float xs[16 * 128];
    __shared__ float ws[128 * 16];
    int t = threadIdx.x;
    int r0 = blockIdx.x * 16;
    for (int i = t; i < 128 * 16 / 4; i += 256)
        *(float4*)&ws[i * 4] = *(const float4*)&W[i * 4];
    for (int i = t; i < 16 * 128 / 4; i += 256) {
        int r = (i * 4) >> 7;
        float4 v = make_float4(0.f, 0.f, 0.f, 0.f);
        if (r0 + r < n) v = *(const float4*)&g_x2[(size_t)r0 * 128 + i * 4];
        *(float4*)&xs[i * 4] = v;
    }
    __syncthreads();
    int row = t >> 4, c = t & 15;
    float acc = 0.f;
#pragma unroll 8
    for (int k = 0; k < 128; k++) acc = fmaf(xs[row * 128 + k], ws[k * 16 + c], acc);
    int grow = r0 + row;
    if (grow < n) g_h2[grow * 16 + c] = acc;
    float pS = acc * asrc[c];
    float pD = acc * adst[c];
#pragma unroll
    for (int step = 1; step < 16; step <<= 1) {
        pS += __shfl_xor_sync(0xFFFFFFFFu, pS, step);
        pD += __shfl_xor_sync(0xFFFFFFFFu, pD, step);
    }
    if (c == 0 && grow < n) {
        g_als2[grow] = pS;
        g_ald2[grow] = pD;
    }
}

// ---------------- Layer-2 aggregation ----------------------------------------
__global__ void k_agg2(const float* __restrict__ b2, float* __restrict__ out, int n) {
    int w = (blockIdx.x * blockDim.x + threadIdx.x) >> 5;
    int lane = threadIdx.x & 31;
    if (w >= n) return;
    int start = g_rowptr[w];
    int end = start + g_deg[w] + 1;
    float ald = g_ald2[w];

    float vcc[4];
    float m = -1e30f;
    int nit = 0;
    for (int jb = start; jb < end; jb += 32, nit++) {
        int j = jb + lane;
        float v = -1e30f;
        if (j < end) v = leaky(g_als2[g_col[j]] + ald);
        if (nit < 4) vcc[nit] = v;
        m = fmaxf(m, v);
    }
#pragma unroll
    for (int off = 16; off; off >>= 1) m = fmaxf(m, __shfl_xor_sync(0xFFFFFFFFu, m, off));
    float d = 0.f;
    nit = 0;
    for (int jb = start; jb < end; jb += 32, nit++) {
        float v;
        if (nit < 4) v = vcc[nit];
        else {
            int j = jb + lane;
            v = -1e30f;
            if (j < end) v = leaky(g_als2[g_col[j]] + ald);
        }
        d += __expf(v - m);
    }
#pragma unroll
    for (int off = 16; off; off >>= 1) d += __shfl_xor_sync(0xFFFFFFFFu, d, off);
    float rd = 1.0f / d;

    int half = lane >> 4, c = lane & 15;
    float acc = 0.f;
    for (int jb = start; jb < end; jb += 32) {
        int j = jb + lane;
        int scol = 0;
        float alpha = 0.f;
        if (j < end) {
            scol = g_col[j];
            alpha = __expf(leaky(g_als2[scol] + ald) - m) * rd;
        }
        int cnt = min(32, end - jb);
        for (int u = 0; u < cnt; u += 2) {
            int uu = u + half;
            int su = uu < cnt ? uu : 0;
            int s = __shfl_sync(0xFFFFFFFFu, scol, su);
            float a = __shfl_sync(0xFFFFFFFFu, alpha, su);
            if (uu < cnt) acc = fmaf(g_h2[s * 16 + c], a, acc);
        }
    }
    acc += __shfl_xor_sync(0xFFFFFFFFu, acc, 16);
    if (half == 0) out[(size_t)w * 16 + c] = acc + b2[c];
}

// ---------------- launch -----------------------------------------------------
extern "C" void kernel_launch(void* const* d_in, const int* in_sizes, int n_in,
                              void* d_out, int out_size) {
    const float* x = (const float*)d_in[0];
    const void* ei = d_in[1];
    const float* W1 = (const float*)d_in[2];
    const float* as1 = (const float*)d_in[3];
    const float* ad1 = (const float*)d_in[4];
    const float* b1 = (const float*)d_in[5];
    const float* W2 = (const float*)d_in[6];
    const float* as2 = (const float*)d_in[7];
    const float* ad2 = (const float*)d_in[8];
    const float* b2 = (const float*)d_in[9];
    float* out = (float*)d_out;

    int N = in_sizes[0] / 128;
    int E = in_sizes[1] / 2;
    if (N > MAXN) N = MAXN;
    if (E > MAXE) E = MAXE;

    k_probe<<<1, 32>>>((const int*)ei, E);
    k_zero_deg<<<(N + 255) / 256, 256>>>(N);
    k_convert<<<(E + 255) / 256, 256>>>(ei, E, N);
    k_alloc<<<(N + 255) / 256, 256>>>(N);
    k_fill<<<(E + 255) / 256, 256>>>(E);

    k_gemm1<<<(N + 127) / 128, 256>>>(x, W1, as1, ad1, N);
    k_agg1<<<(N + 7) / 8, 256>>>(b1, N);
    k_gemm2<<<(N + 15) / 16, 256>>>(W2, as2, ad2, N);
    k_agg2<<<(N + 7) / 8, 256>>>(b2, out, N);
}

// round 9
// speedup vs baseline: 1.4144x; 1.1595x over previous
#include <cuda_runtime.h>

#define MAXN 100000
#define MAXE 1600000
#define MAXTOT (MAXN + MAXE)
#define NEG_SLOPE 0.2f

// ---------------- scratch ---------------------------------------------------
__device__ __align__(16) float g_h1[MAXN * 128];
__device__ __align__(16) float g_als1[MAXN * 4];
__device__ __align__(16) float g_ald1[MAXN * 4];
__device__ __align__(16) float g_x2[MAXN * 128];
__device__ __align__(16) float g_h2[MAXN * 16];
__device__ float g_als2[MAXN];
__device__ float g_ald2[MAXN];
__device__ int g_deg[MAXN];
__device__ int g_rowptr[MAXN];     // row START only (order-free allocation)
__device__ int g_cursor[MAXN];
__device__ int g_col[MAXTOT];
__device__ int g_src[MAXE];
__device__ int g_dst[MAXE];
__device__ int g_is64;
__device__ int g_total;

// ---------------- f32x2 helpers ---------------------------------------------
__device__ __forceinline__ unsigned long long pack2(float a, float b) {
    unsigned long long r;
    asm("mov.b64 %0, {%1, %2};" : "=l"(r) : "f"(a), "f"(b));
    return r;
}
__device__ __forceinline__ void fma2(unsigned long long& d, unsigned long long a,
                                     unsigned long long b) {
    asm("fma.rn.f32x2 %0, %1, %2, %0;" : "+l"(d) : "l"(a), "l"(b));
}
__device__ __forceinline__ float2 unpack2(unsigned long long v) {
    float2 f;
    asm("mov.b64 {%0, %1}, %2;" : "=f"(f.x), "=f"(f.y) : "l"(v));
    return f;
}

__device__ __forceinline__ float leaky(float e) { return e > 0.f ? e : NEG_SLOPE * e; }

// ---------------- edge-index probe / normalize / count -----------------------
__global__ void k_probe(const int* __restrict__ ei32, int E) {
    if (threadIdx.x == 0 && blockIdx.x == 0) {
        int cnt = E < 64 ? E : 64;
        int zeros = 0;
        for (int i = 0; i < cnt; i++) zeros += (ei32[2 * i + 1] == 0) ? 1 : 0;
        g_is64 = (zeros == cnt) ? 1 : 0;
        g_total = 0;
    }
}

__global__ void k_zero_deg(int n) {
    int i = blockIdx.x * blockDim.x + threadIdx.x;
    if (i < n) g_deg[i] = 0;
}

__global__ void k_convert(const void* __restrict__ ei, int E, int N) {
    int e = blockIdx.x * blockDim.x + threadIdx.x;
    if (e >= E) return;
    int s, d;
    if (g_is64) {
        const long long* p = (const long long*)ei;
        s = (int)p[e];
        d = (int)p[E + e];
    } else {
        const int* p = (const int*)ei;
        s = p[e];
        d = p[E + e];
    }
    s = min(max(s, 0), N - 1);
    d = min(max(d, 0), N - 1);
    g_src[e] = s;
    g_dst[e] = d;
    atomicAdd(&g_deg[d], 1);
}

// parallel segment allocator (order-free CSR)
__global__ void k_alloc(int n) {
    int i = blockIdx.x * blockDim.x + threadIdx.x;
    int lane = threadIdx.x & 31;
    int v = (i < n) ? g_deg[i] + 1 : 0;
    int incl = v;
#pragma unroll
    for (int off = 1; off < 32; off <<= 1) {
        int t = __shfl_up_sync(0xFFFFFFFFu, incl, off);
        if (lane >= off) incl += t;
    }
    int tot = __shfl_sync(0xFFFFFFFFu, incl, 31);
    int base = 0;
    if (lane == 0) base = atomicAdd(&g_total, tot);
    base = __shfl_sync(0xFFFFFFFFu, base, 0);
    int pos = base + incl - v;
    if (i < n) {
        g_rowptr[i] = pos;
        g_col[pos] = i;          // self loop occupies first slot
        g_cursor[i] = pos + 1;
    }
}

__global__ void k_fill(int E) {
    int e = blockIdx.x * blockDim.x + threadIdx.x;
    if (e < E) {
        int pos = atomicAdd(&g_cursor[g_dst[e]], 1);
        g_col[pos] = g_src[e];
    }
}

// ---------------- GEMM1: 128x128 tile, 8x8 per-thread register blocking ------
__global__ void k_gemm1(const float* __restrict__ x, const float* __restrict__ W,
                        const float* __restrict__ asrc, const float* __restrict__ adst,
                        int n) {
    __shared__ float xs[128 * 33];
    __shared__ float ws[32 * 128];
    int t = threadIdx.x;
    int tx = t & 15, ty = t >> 4;
    int row0 = blockIdx.x * 128;

    unsigned long long acc[8][4];
#pragma unroll
    for (int i = 0; i < 8; i++)
#pragma unroll
        for (int j = 0; j < 4; j++) acc[i][j] = pack2(0.f, 0.f);

    for (int kc = 0; kc < 128; kc += 32) {
        for (int i = t; i < 1024; i += 256) {
            int r = i >> 3, cq = i & 7;
            float4 v = make_float4(0.f, 0.f, 0.f, 0.f);
            if (row0 + r < n)
                v = *(const float4*)&x[(size_t)(row0 + r) * 128 + kc + cq * 4];
            float* p = &xs[r * 33 + cq * 4];
            p[0] = v.x; p[1] = v.y; p[2] = v.z; p[3] = v.w;
        }
        for (int i = t; i < 1024; i += 256)
            *(float4*)&ws[i * 4] = *(const float4*)&W[(size_t)kc * 128 + i * 4];
        __syncthreads();
#pragma unroll 4
        for (int k = 0; k < 32; k++) {
            float4 wa = *(const float4*)&ws[k * 128 + tx * 8];
            float4 wb = *(const float4*)&ws[k * 128 + tx * 8 + 4];
            unsigned long long wp0 = pack2(wa.x, wa.y);
            unsigned long long wp1 = pack2(wa.z, wa.w);
            unsigned long long wp2 = pack2(wb.x, wb.y);
            unsigned long long wp3 = pack2(wb.z, wb.w);
#pragma unroll
            for (int i = 0; i < 8; i++) {
                float xv = xs[(ty * 8 + i) * 33 + k];
                unsigned long long xp = pack2(xv, xv);
                fma2(acc[i][0], xp, wp0);
                fma2(acc[i][1], xp, wp1);
                fma2(acc[i][2], xp, wp2);
                fma2(acc[i][3], xp, wp3);
            }
        }
        __syncthreads();
    }

    int h0 = tx >> 2;
    int base = (tx & 3) * 8;
    float aS[8], aD[8];
#pragma unroll
    for (int j = 0; j < 8; j++) {
        aS[j] = asrc[h0 * 32 + base + j];
        aD[j] = adst[h0 * 32 + base + j];
    }
#pragma unroll
    for (int i = 0; i < 8; i++) {
        int row = row0 + ty * 8 + i;
        float2 p0 = unpack2(acc[i][0]);
        float2 p1 = unpack2(acc[i][1]);
        float2 p2 = unpack2(acc[i][2]);
        float2 p3 = unpack2(acc[i][3]);
        float hv[8] = {p0.x, p0.y, p1.x, p1.y, p2.x, p2.y, p3.x, p3.y};
        if (row < n) {
            *(float4*)&g_h1[(size_t)row * 128 + tx * 8] =
                make_float4(hv[0], hv[1], hv[2], hv[3]);
            *(float4*)&g_h1[(size_t)row * 128 + tx * 8 + 4] =
                make_float4(hv[4], hv[5], hv[6], hv[7]);
        }
        float pS = 0.f, pD = 0.f;
#pragma unroll
        for (int j = 0; j < 8; j++) {
            pS = fmaf(hv[j], aS[j], pS);
            pD = fmaf(hv[j], aD[j], pD);
        }
        pS += __shfl_xor_sync(0xFFFFFFFFu, pS, 1);
        pD += __shfl_xor_sync(0xFFFFFFFFu, pD, 1);
        pS += __shfl_xor_sync(0xFFFFFFFFu, pS, 2);
        pD += __shfl_xor_sync(0xFFFFFFFFu, pD, 2);
        if ((tx & 3) == 0 && row < n) {
            g_als1[row * 4 + h0] = pS;
            g_ald1[row * 4 + h0] = pD;
        }
    }
}

// ---------------- Layer-1 aggregation: SINGLE-PASS unnormalized softmax ------
// Valid because |logit| <= ~10 << 88 (no exp overflow). out = (sum ex*h)/(sum ex).
__global__ void k_agg1(const float* __restrict__ b1, int n) {
    int w = (blockIdx.x * blockDim.x + threadIdx.x) >> 5;
    int lane = threadIdx.x & 31;
    if (w >= n) return;
    int start = g_rowptr[w];
    int end = start + g_deg[w] + 1;
    float4 aldv = *(const float4*)&g_ald1[w * 4];
    int hd = lane & 3;          // head handled in the exp phase
    float aldd = (hd == 0) ? aldv.x : (hd == 1) ? aldv.y : (hd == 2) ? aldv.z : aldv.w;
    int hg = lane >> 3;         // head owning this lane's output columns
    int c = lane << 2;          // output cols c..c+3

    float den = 0.f;
    float a0 = 0.f, a1 = 0.f, a2 = 0.f, a3 = 0.f;
    for (int jb = start; jb < end; jb += 8) {
        // phase 1: lane L handles (edge jb+(L>>2), head L&3)
        int j = jb + (lane >> 2);
        int scol = 0;
        float ex = 0.f;
        if (j < end) {
            scol = g_col[j];                       // 4 lanes/edge, same addr (broadcast)
            ex = __expf(leaky(g_als1[scol * 4 + hd] + aldd));
            den += ex;
        }
        // phase 2: weighted gather of up to 8 rows, MLP-8
        int cnt = min(8, end - jb);
        if (cnt == 8) {
#pragma unroll
            for (int u = 0; u < 8; u++) {
                int s = __shfl_sync(0xFFFFFFFFu, scol, u * 4);
                float a = __shfl_sync(0xFFFFFFFFu, ex, u * 4 + hg);
                float4 hv = *(const float4*)&g_h1[(size_t)s * 128 + c];
                a0 = fmaf(hv.x, a, a0);
                a1 = fmaf(hv.y, a, a1);
                a2 = fmaf(hv.z, a, a2);
                a3 = fmaf(hv.w, a, a3);
            }
        } else {
            for (int u = 0; u < cnt; u++) {
                int s = __shfl_sync(0xFFFFFFFFu, scol, u * 4);
                float a = __shfl_sync(0xFFFFFFFFu, ex, u * 4 + hg);
                float4 hv = *(const float4*)&g_h1[(size_t)s * 128 + c];
                a0 = fmaf(hv.x, a, a0);
                a1 = fmaf(hv.y, a, a1);
                a2 = fmaf(hv.z, a, a2);
                a3 = fmaf(hv.w, a, a3);
            }
        }
    }
    // reduce denominator within head class (lanes with equal hd)
    den += __shfl_xor_sync(0xFFFFFFFFu, den, 4);
    den += __shfl_xor_sync(0xFFFFFFFFu, den, 8);
    den += __shfl_xor_sync(0xFFFFFFFFu, den, 16);
    float rd = 1.0f / den;                          // this lane: head hd
    float rdg = __shfl_sync(0xFFFFFFFFu, rd, hg);   // lane hg holds head hg
    float4 bb = *(const float4*)&b1[c];
    float4 o;
    o.x = fmaxf(fmaf(a0, rdg, bb.x), 0.f);
    o.y = fmaxf(fmaf(a1, rdg, bb.y), 0.f);
    o.z = fmaxf(fmaf(a2, rdg, bb.z), 0.f);
    o.w = fmaxf(fmaf(a3, rdg, bb.w), 0.f);
    *(float4*)&g_x2[(size_t)w * 128 + c] = o;
}

// ---------------- GEMM2: h2 = x2 @ W2 [128,16] + fused dots ------------------
__global__ void k_gemm2(const float* __restrict__ W, const float* __restrict__ asrc,
                        const float* __restrict__ adst, int n) {
    __shared__ float xs[16 * 128];
    __shared__ float ws[128 * 16];
    int t = threadIdx.x;
    int r0 = blockIdx.x * 16;
    for (int i = t; i < 128 * 16 / 4; i += 256)
        *(float4*)&ws[i * 4] = *(const float4*)&W[i * 4];
    for (int i = t; i < 16 * 128 / 4; i += 256) {
        int r = (i * 4) >> 7;
        float4 v = make_float4(0.f, 0.f, 0.f, 0.f);
        if (r0 + r < n) v = *(const float4*)&g_x2[(size_t)r0 * 128 + i * 4];
        *(float4*)&xs[i * 4] = v;
    }
    __syncthreads();
    int row = t >> 4, c = t & 15;
    float acc = 0.f;
#pragma unroll 8
    for (int k = 0; k < 128; k++) acc = fmaf(xs[row * 128 + k], ws[k * 16 + c], acc);
    int grow = r0 + row;
    if (grow < n) g_h2[grow * 16 + c] = acc;
    float pS = acc * asrc[c];
    float pD = acc * adst[c];
#pragma unroll
    for (int step = 1; step < 16; step <<= 1) {
        pS += __shfl_xor_sync(0xFFFFFFFFu, pS, step);
        pD += __shfl_xor_sync(0xFFFFFFFFu, pD, step);
    }
    if (c == 0 && grow < n) {
        g_als2[grow] = pS;
        g_ald2[grow] = pD;
    }
}

// ---------------- Layer-2 aggregation: single-pass ---------------------------
__global__ void k_agg2(const float* __restrict__ b2, float* __restrict__ out, int n) {
    int w = (blockIdx.x * blockDim.x + threadIdx.x) >> 5;
    int lane = threadIdx.x & 31;
    if (w >= n) return;
    int start = g_rowptr[w];
    int end = start + g_deg[w] + 1;
    float ald = g_ald2[w];

    int half = lane >> 4, c = lane & 15;
    float den = 0.f, acc = 0.f;
    for (int jb = start; jb < end; jb += 32) {
        int j = jb + lane;
        int scol = 0;
        float ex = 0.f;
        if (j < end) {
            scol = g_col[j];
            ex = __expf(leaky(g_als2[scol] + ald));
            den += ex;
        }
        int cnt = min(32, end - jb);
        for (int u = 0; u < cnt; u += 2) {
            int uu = u + half;
            int su = uu < cnt ? uu : 0;
            int s = __shfl_sync(0xFFFFFFFFu, scol, su);
            float a = __shfl_sync(0xFFFFFFFFu, ex, su);
            if (uu < cnt) acc = fmaf(g_h2[s * 16 + c], a, acc);
        }
    }
#pragma unroll
    for (int off = 16; off; off >>= 1) den += __shfl_xor_sync(0xFFFFFFFFu, den, off);
    float rd = 1.0f / den;
    acc += __shfl_xor_sync(0xFFFFFFFFu, acc, 16);
    if (half == 0) out[(size_t)w * 16 + c] = fmaf(acc, rd, b2[c]);
}

// ---------------- launch -----------------------------------------------------
extern "C" void kernel_launch(void* const* d_in, const int* in_sizes, int n_in,
                              void* d_out, int out_size) {
    const float* x = (const float*)d_in[0];
    const void* ei = d_in[1];
    const float* W1 = (const float*)d_in[2];
    const float* as1 = (const float*)d_in[3];
    const float* ad1 = (const float*)d_in[4];
    const float* b1 = (const float*)d_in[5];
    const float* W2 = (const float*)d_in[6];
    const float* as2 = (const float*)d_in[7];
    const float* ad2 = (const float*)d_in[8];
    const float* b2 = (const float*)d_in[9];
    float* out = (float*)d_out;

    int N = in_sizes[0] / 128;
    int E = in_sizes[1] / 2;
    if (N > MAXN) N = MAXN;
    if (E > MAXE) E = MAXE;

    // one-time handles for the parallel branch (no device memory involved)
    static cudaStream_t s2 = nullptr;
    static cudaEvent_t evRoot = nullptr, evG1 = nullptr;
    if (s2 == nullptr) {
        cudaStreamCreateWithFlags(&s2, cudaStreamNonBlocking);
        cudaEventCreateWithFlags(&evRoot, cudaEventDisableTiming);
        cudaEventCreateWithFlags(&evG1, cudaEventDisableTiming);
    }

    // branch: GEMM1 (reads only inputs) runs parallel to the CSR build
    cudaEventRecord(evRoot, 0);
    cudaStreamWaitEvent(s2, evRoot, 0);
    k_gemm1<<<(N + 127) / 128, 256, 0, s2>>>(x, W1, as1, ad1, N);
    cudaEventRecord(evG1, s2);

    // CSR build chain on the default stream
    k_probe<<<1, 32>>>((const int*)ei, E);
    k_zero_deg<<<(N + 255) / 256, 256>>>(N);
    k_convert<<<(E + 255) / 256, 256>>>(ei, E, N);
    k_alloc<<<(N + 255) / 256, 256>>>(N);
    k_fill<<<(E + 255) / 256, 256>>>(E);

    // join, then the rest of the pipeline
    cudaStreamWaitEvent(0, evG1, 0);
    k_agg1<<<(N + 7) / 8, 256>>>(b1, N);
    k_gemm2<<<(N + 15) / 16, 256>>>(W2, as2, ad2, N);
    k_agg2<<<(N + 7) / 8, 256>>>(b2, out, N);
}

// round 12
// speedup vs baseline: 2.0712x; 1.4644x over previous
#include <cuda_runtime.h>
#include <cuda_fp16.h>

#define MAXN 100000
#define MAXE 1600000
#define MAXTOT (MAXN + MAXE)
#define NEG_SLOPE 0.2f

// ---------------- scratch ---------------------------------------------------
__device__ __align__(16) __half2 g_h1h[MAXN * 64];   // layer-1 features, fp16
__device__ __align__(16) float g_als1[MAXN * 4];
__device__ __align__(16) float g_ald1[MAXN * 4];
__device__ __align__(16) float g_x2[MAXN * 128];
__device__ __align__(16) float g_h2[MAXN * 16];
__device__ float g_als2[MAXN];
__device__ float g_ald2[MAXN];
__device__ int g_deg[MAXN];
__device__ int g_rowptr[MAXN];
__device__ int g_cursor[MAXN];
__device__ int g_col[MAXTOT];
__device__ int g_src[MAXE];
__device__ int g_dst[MAXE];
__device__ int g_is64;
__device__ int g_total;

// ---------------- f32x2 helpers ---------------------------------------------
__device__ __forceinline__ unsigned long long pack2(float a, float b) {
    unsigned long long r;
    asm("mov.b64 %0, {%1, %2};" : "=l"(r) : "f"(a), "f"(b));
    return r;
}
__device__ __forceinline__ void fma2(unsigned long long& d, unsigned long long a,
                                     unsigned long long b) {
    asm("fma.rn.f32x2 %0, %1, %2, %0;" : "+l"(d) : "l"(a), "l"(b));
}
__device__ __forceinline__ float2 unpack2(unsigned long long v) {
    float2 f;
    asm("mov.b64 {%0, %1}, %2;" : "=f"(f.x), "=f"(f.y) : "l"(v));
    return f;
}

__device__ __forceinline__ float leaky(float e) { return e > 0.f ? e : NEG_SLOPE * e; }

// ---------------- edge-index probe / normalize / count -----------------------
__global__ void k_probe(const int* __restrict__ ei32, int E) {
    if (threadIdx.x == 0 && blockIdx.x == 0) {
        int cnt = E < 64 ? E : 64;
        int zeros = 0;
        for (int i = 0; i < cnt; i++) zeros += (ei32[2 * i + 1] == 0) ? 1 : 0;
        g_is64 = (zeros == cnt) ? 1 : 0;
        g_total = 0;
    }
}

__global__ void k_zero_deg(int n) {
    int i = blockIdx.x * blockDim.x + threadIdx.x;
    if (i < n) g_deg[i] = 0;
}

__global__ void k_convert(const void* __restrict__ ei, int E, int N) {
    int e = blockIdx.x * blockDim.x + threadIdx.x;
    if (e >= E) return;
    int s, d;
    if (g_is64) {
        const long long* p = (const long long*)ei;
        s = (int)p[e];
        d = (int)p[E + e];
    } else {
        const int* p = (const int*)ei;
        s = p[e];
        d = p[E + e];
    }
    s = min(max(s, 0), N - 1);
    d = min(max(d, 0), N - 1);
    g_src[e] = s;
    g_dst[e] = d;
    atomicAdd(&g_deg[d], 1);
}

// parallel segment allocator (order-free CSR)
__global__ void k_alloc(int n) {
    int i = blockIdx.x * blockDim.x + threadIdx.x;
    int lane = threadIdx.x & 31;
    int v = (i < n) ? g_deg[i] + 1 : 0;
    int incl = v;
#pragma unroll
    for (int off = 1; off < 32; off <<= 1) {
        int t = __shfl_up_sync(0xFFFFFFFFu, incl, off);
        if (lane >= off) incl += t;
    }
    int tot = __shfl_sync(0xFFFFFFFFu, incl, 31);
    int base = 0;
    if (lane == 0) base = atomicAdd(&g_total, tot);
    base = __shfl_sync(0xFFFFFFFFu, base, 0);
    int pos = base + incl - v;
    if (i < n) {
        g_rowptr[i] = pos;
        g_col[pos] = i;
        g_cursor[i] = pos + 1;
    }
}

__global__ void k_fill(int E) {
    int e = blockIdx.x * blockDim.x + threadIdx.x;
    if (e < E) {
        int pos = atomicAdd(&g_cursor[g_dst[e]], 1);
        g_col[pos] = g_src[e];
    }
}

// ---------------- GEMM1: 128x128 tile, 8x8 register blocking, fp16 h1 out ----
__global__ void k_gemm1(const float* __restrict__ x, const float* __restrict__ W,
                        const float* __restrict__ asrc, const float* __restrict__ adst,
                        int n) {
    __shared__ float xs[128 * 33];
    __shared__ float ws[32 * 128];
    int t = threadIdx.x;
    int tx = t & 15, ty = t >> 4;
    int row0 = blockIdx.x * 128;

    unsigned long long acc[8][4];
#pragma unroll
    for (int i = 0; i < 8; i++)
#pragma unroll
        for (int j = 0; j < 4; j++) acc[i][j] = pack2(0.f, 0.f);

    for (int kc = 0; kc < 128; kc += 32) {
        for (int i = t; i < 1024; i += 256) {
            int r = i >> 3, cq = i & 7;
            float4 v = make_float4(0.f, 0.f, 0.f, 0.f);
            if (row0 + r < n)
                v = *(const float4*)&x[(size_t)(row0 + r) * 128 + kc + cq * 4];
            float* p = &xs[r * 33 + cq * 4];
            p[0] = v.x; p[1] = v.y; p[2] = v.z; p[3] = v.w;
        }
        for (int i = t; i < 1024; i += 256)
            *(float4*)&ws[i * 4] = *(const float4*)&W[(size_t)kc * 128 + i * 4];
        __syncthreads();
#pragma unroll 4
        for (int k = 0; k < 32; k++) {
            float4 wa = *(const float4*)&ws[k * 128 + tx * 8];
            float4 wb = *(const float4*)&ws[k * 128 + tx * 8 + 4];
            unsigned long long wp0 = pack2(wa.x, wa.y);
            unsigned long long wp1 = pack2(wa.z, wa.w);
            unsigned long long wp2 = pack2(wb.x, wb.y);
            unsigned long long wp3 = pack2(wb.z, wb.w);
#pragma unroll
            for (int i = 0; i < 8; i++) {
                float xv = xs[(ty * 8 + i) * 33 + k];
                unsigned long long xp = pack2(xv, xv);
                fma2(acc[i][0], xp, wp0);
                fma2(acc[i][1], xp, wp1);
                fma2(acc[i][2], xp, wp2);
                fma2(acc[i][3], xp, wp3);
            }
        }
        __syncthreads();
    }

    int h0 = tx >> 2;
    int base = (tx & 3) * 8;
    float aS[8], aD[8];
#pragma unroll
    for (int j = 0; j < 8; j++) {
        aS[j] = asrc[h0 * 32 + base + j];
        aD[j] = adst[h0 * 32 + base + j];
    }
#pragma unroll
    for (int i = 0; i < 8; i++) {
        int row = row0 + ty * 8 + i;
        float2 p0 = unpack2(acc[i][0]);
        float2 p1 = unpack2(acc[i][1]);
        float2 p2 = unpack2(acc[i][2]);
        float2 p3 = unpack2(acc[i][3]);
        float hv[8] = {p0.x, p0.y, p1.x, p1.y, p2.x, p2.y, p3.x, p3.y};
        if (row < n) {
            __half2 hh[4];
            hh[0] = __floats2half2_rn(hv[0], hv[1]);
            hh[1] = __floats2half2_rn(hv[2], hv[3]);
            hh[2] = __floats2half2_rn(hv[4], hv[5]);
            hh[3] = __floats2half2_rn(hv[6], hv[7]);
            *(float4*)&g_h1h[(size_t)row * 64 + tx * 4] = *(float4*)hh;
        }
        float pS = 0.f, pD = 0.f;
#pragma unroll
        for (int j = 0; j < 8; j++) {
            pS = fmaf(hv[j], aS[j], pS);
            pD = fmaf(hv[j], aD[j], pD);
        }
        pS += __shfl_xor_sync(0xFFFFFFFFu, pS, 1);
        pD += __shfl_xor_sync(0xFFFFFFFFu, pD, 1);
        pS += __shfl_xor_sync(0xFFFFFFFFu, pS, 2);
        pD += __shfl_xor_sync(0xFFFFFFFFu, pD, 2);
        if ((tx & 3) == 0 && row < n) {
            g_als1[row * 4 + h0] = pS;
            g_ald1[row * 4 + h0] = pD;
        }
    }
}

// ---------------- Layer-1 aggregation: single-pass, fp16 gather --------------
__global__ void k_agg1(const float* __restrict__ b1, int n) {
    int w = (blockIdx.x * blockDim.x + threadIdx.x) >> 5;
    int lane = threadIdx.x & 31;
    if (w >= n) return;
    int start = g_rowptr[w];
    int end = start + g_deg[w] + 1;
    float4 aldv = *(const float4*)&g_ald1[w * 4];
    int hd = lane & 3;
    float aldd = (hd == 0) ? aldv.x : (hd == 1) ? aldv.y : (hd == 2) ? aldv.z : aldv.w;
    int hg = lane >> 3;
    int c = lane << 2;              // output cols c..c+3 -> half2 idx lane*2

    float den = 0.f;
    float a0 = 0.f, a1 = 0.f, a2 = 0.f, a3 = 0.f;
    for (int jb = start; jb < end; jb += 8) {
        int j = jb + (lane >> 2);
        int scol = 0;
        float ex = 0.f;
        if (j < end) {
            scol = g_col[j];
            ex = __expf(leaky(g_als1[scol * 4 + hd] + aldd));
            den += ex;
        }
        int cnt = min(8, end - jb);
        if (cnt == 8) {
#pragma unroll
            for (int u = 0; u < 8; u++) {
                int s = __shfl_sync(0xFFFFFFFFu, scol, u * 4);
                float a = __shfl_sync(0xFFFFFFFFu, ex, u * 4 + hg);
                uint2 raw = *(const uint2*)&g_h1h[(size_t)s * 64 + lane * 2];
                float2 f0 = __half22float2(*(__half2*)&raw.x);
                float2 f1 = __half22float2(*(__half2*)&raw.y);
                a0 = fmaf(f0.x, a, a0);
                a1 = fmaf(f0.y, a, a1);
                a2 = fmaf(f1.x, a, a2);
                a3 = fmaf(f1.y, a, a3);
            }
        } else {
            for (int u = 0; u < cnt; u++) {
                int s = __shfl_sync(0xFFFFFFFFu, scol, u * 4);
                float a = __shfl_sync(0xFFFFFFFFu, ex, u * 4 + hg);
                uint2 raw = *(const uint2*)&g_h1h[(size_t)s * 64 + lane * 2];
                float2 f0 = __half22float2(*(__half2*)&raw.x);
                float2 f1 = __half22float2(*(__half2*)&raw.y);
                a0 = fmaf(f0.x, a, a0);
                a1 = fmaf(f0.y, a, a1);
                a2 = fmaf(f1.x, a, a2);
                a3 = fmaf(f1.y, a, a3);
            }
        }
    }
    den += __shfl_xor_sync(0xFFFFFFFFu, den, 4);
    den += __shfl_xor_sync(0xFFFFFFFFu, den, 8);
    den += __shfl_xor_sync(0xFFFFFFFFu, den, 16);
    float rd = 1.0f / den;
    float rdg = __shfl_sync(0xFFFFFFFFu, rd, hg);
    float4 bb = *(const float4*)&b1[c];
    float4 o;
    o.x = fmaxf(fmaf(a0, rdg, bb.x), 0.f);
    o.y = fmaxf(fmaf(a1, rdg, bb.y), 0.f);
    o.z = fmaxf(fmaf(a2, rdg, bb.z), 0.f);
    o.w = fmaxf(fmaf(a3, rdg, bb.w), 0.f);
    *(float4*)&g_x2[(size_t)w * 128 + c] = o;
}

// ---------------- GEMM2: h2 = x2 @ W2 [128,16] + fused dots ------------------
__global__ void k_gemm2(const float* __restrict__ W, const float* __restrict__ asrc,
                        const float* __restrict__ adst, int n) {
    __shared__ float xs[16 * 128];
    __shared__ float ws[128 * 16];
    int t = threadIdx.x;
    int r0 = blockIdx.x * 16;
    for (int i = t; i < 128 * 16 / 4; i += 256)
        *(float4*)&ws[i * 4] = *(const float4*)&W[i * 4];
    for (int i = t; i < 16 * 128 / 4; i += 256) {
        int r = (i * 4) >> 7;
        float4 v = make_float4(0.f, 0.f, 0.f, 0.f);
        if (r0 + r < n) v = *(const float4*)&g_x2[(size_t)r0 * 128 + i * 4];
        *(float4*)&xs[i * 4] = v;
    }
    __syncthreads();
    int row = t >> 4, c = t & 15;
    float acc = 0.f;
#pragma unroll 8
    for (int k = 0; k < 128; k++) acc = fmaf(xs[row * 128 + k], ws[k * 16 + c], acc);
    int grow = r0 + row;
    if (grow < n) g_h2[grow * 16 + c] = acc;
    float pS = acc * asrc[c];
    float pD = acc * adst[c];
#pragma unroll
    for (int step = 1; step < 16; step <<= 1) {
        pS += __shfl_xor_sync(0xFFFFFFFFu, pS, step);
        pD += __shfl_xor_sync(0xFFFFFFFFu, pD, step);
    }
    if (c == 0 && grow < n) {
        g_als2[grow] = pS;
        g_ald2[grow] = pD;
    }
}

// ---------------- Layer-2 aggregation: single-pass ---------------------------
__global__ void k_agg2(const float* __restrict__ b2, float* __restrict__ out, int n) {
    int w = (blockIdx.x * blockDim.x + threadIdx.x) >> 5;
    int lane = threadIdx.x & 31;
    if (w >= n) return;
    int start = g_rowptr[w];
    int end = start + g_deg[w] + 1;
    float ald = g_ald2[w];

    int half = lane >> 4, c = lane & 15;
    float den = 0.f, acc = 0.f;
    for (int jb = start; jb < end; jb += 32) {
        int j = jb + lane;
        int scol = 0;
        float ex = 0.f;
        if (j < end) {
            scol = g_col[j];
            ex = __expf(leaky(g_als2[scol] + ald));
            den += ex;
        }
        int cnt = min(32, end - jb);
        for (int u = 0; u < cnt; u += 2) {
            int uu = u + half;
            int su = uu < cnt ? uu : 0;
            int s = __shfl_sync(0xFFFFFFFFu, scol, su);
            float a = __shfl_sync(0xFFFFFFFFu, ex, su);
            if (uu < cnt) acc = fmaf(g_h2[s * 16 + c], a, acc);
        }
    }
#pragma unroll
    for (int off = 16; off; off >>= 1) den += __shfl_xor_sync(0xFFFFFFFFu, den, off);
    float rd = 1.0f / den;
    acc += __shfl_xor_sync(0xFFFFFFFFu, acc, 16);
    if (half == 0) out[(size_t)w * 16 + c] = fmaf(acc, rd, b2[c]);
}

// ---------------- launch -----------------------------------------------------
extern "C" void kernel_launch(void* const* d_in, const int* in_sizes, int n_in,
                              void* d_out, int out_size) {
    const float* x = (const float*)d_in[0];
    const void* ei = d_in[1];
    const float* W1 = (const float*)d_in[2];
    const float* as1 = (const float*)d_in[3];
    const float* ad1 = (const float*)d_in[4];
    const float* b1 = (const float*)d_in[5];
    const float* W2 = (const float*)d_in[6];
    const float* as2 = (const float*)d_in[7];
    const float* ad2 = (const float*)d_in[8];
    const float* b2 = (const float*)d_in[9];
    float* out = (float*)d_out;

    int N = in_sizes[0] / 128;
    int E = in_sizes[1] / 2;
    if (N > MAXN) N = MAXN;
    if (E > MAXE) E = MAXE;

    static cudaStream_t s2 = nullptr;
    static cudaEvent_t evRoot = nullptr, evG1 = nullptr;
    if (s2 == nullptr) {
        cudaStreamCreateWithFlags(&s2, cudaStreamNonBlocking);
        cudaEventCreateWithFlags(&evRoot, cudaEventDisableTiming);
        cudaEventCreateWithFlags(&evG1, cudaEventDisableTiming);
    }

    // branch: GEMM1 runs parallel to the CSR build
    cudaEventRecord(evRoot, 0);
    cudaStreamWaitEvent(s2, evRoot, 0);
    k_gemm1<<<(N + 127) / 128, 256, 0, s2>>>(x, W1, as1, ad1, N);
    cudaEventRecord(evG1, s2);

    k_probe<<<1, 32>>>((const int*)ei, E);
    k_zero_deg<<<(N + 255) / 256, 256>>>(N);
    k_convert<<<(E + 255) / 256, 256>>>(ei, E, N);
    k_alloc<<<(N + 255) / 256, 256>>>(N);
    k_fill<<<(E + 255) / 256, 256>>>(E);

    cudaStreamWaitEvent(0, evG1, 0);
    k_agg1<<<(N + 7) / 8, 256>>>(b1, N);
    k_gemm2<<<(N + 15) / 16, 256>>>(W2, as2, ad2, N);
    k_agg2<<<(N + 7) / 8, 256>>>(b2, out, N);
}